// round 9
// baseline (speedup 1.0000x reference)
#include <cuda_runtime.h>
#include <stdint.h>

// ---------------------------------------------------------------------------
// TiledFeaturesMap: B=4, N=2048, C=512, FS=1, T_SZ=9, T_STEP=6, T_CUT=2
// Output: float32 [ f_ns (K) | f_tiles (K*512*81) ], K = out_size/41473.
// tiles_kernel: per (tile, 64-ch chunk) block; emit split between one TMA
// bulk store (async engine) and warp STG.128 (LSU path) running concurrently.
// ---------------------------------------------------------------------------

#define NB 4
#define NP 2048
#define NC 512
#define TSZ 9
#define CELLS 81
#define TILE_ELEMS 41472
#define SLOTMAX 512
#define CHUNK 64                        // channels per block
#define NCHUNK (NC / CHUNK)             // 8
#define CHUNK_ELEMS (CHUNK * CELLS)     // 5184

__device__ int g_selcnt[NB];
__device__ int g_cnt[NB * SLOTMAX];
__device__ int g_list[NB * SLOTMAX * CELLS];   // (cell<<16)|n

// ---------------------------------------------------------------------------
// setup: 4 blocks (one per batch) x 512 threads.
// ---------------------------------------------------------------------------
__global__ __launch_bounds__(512) void setup_kernel(const void* __restrict__ ys_raw,
                                                    const void* __restrict__ xs_raw)
{
    const int b = blockIdx.x;
    const int tid = threadIdx.x;

    __shared__ int s_bad, s_ymin, s_ymax, s_xmin, s_xmax;
    __shared__ unsigned char s_mask[512];
    __shared__ short s_slot[512];
    __shared__ int s_cnt[512];
    __shared__ int s_ws[16];
    __shared__ int s_nH, s_nW, s_T;

    if (tid == 0) { s_bad = 0; s_ymin = 1 << 30; s_ymax = -1; s_xmin = 1 << 30; s_xmax = -1; }
    s_mask[tid] = 0;
    s_cnt[tid] = 0;
    __syncthreads();

    // dtype detect (int64 LE: odd 32-bit words all 0)
    {
        const int* yw = (const int*)ys_raw;
        const int* xw = (const int*)xs_raw;
        int bad = 0;
        for (int i = b * 2 * NP + 1 + 2 * tid; i < (b + 1) * 2 * NP; i += 1024)
            bad |= yw[i] | xw[i];
        bad = __reduce_or_sync(0xffffffffu, bad);
        if ((tid & 31) == 0 && bad) atomicOr(&s_bad, 1);
    }
    __syncthreads();
    const bool is64 = (s_bad == 0);

    int py[4], px[4];
#pragma unroll
    for (int j = 0; j < 4; j++) {
        const int idx = b * NP + tid + j * 512;
        if (is64) {
            py[j] = (int)((const long long*)ys_raw)[idx];
            px[j] = (int)((const long long*)xs_raw)[idx];
        } else {
            py[j] = ((const int*)ys_raw)[idx];
            px[j] = ((const int*)xs_raw)[idx];
        }
    }
    {
        int ymn = py[0], ymx = py[0], xmn = px[0], xmx = px[0];
#pragma unroll
        for (int j = 1; j < 4; j++) {
            ymn = min(ymn, py[j]); ymx = max(ymx, py[j]);
            xmn = min(xmn, px[j]); xmx = max(xmx, px[j]);
        }
        ymn = __reduce_min_sync(0xffffffffu, ymn);
        ymx = __reduce_max_sync(0xffffffffu, ymx);
        xmn = __reduce_min_sync(0xffffffffu, xmn);
        xmx = __reduce_max_sync(0xffffffffu, xmx);
        if ((tid & 31) == 0) {
            atomicMin(&s_ymin, ymn); atomicMax(&s_ymax, ymx);
            atomicMin(&s_xmin, xmn); atomicMax(&s_xmax, xmx);
        }
    }
    __syncthreads();
    if (tid == 0) {
        s_nH = (s_ymax - s_ymin + 1) / 6 + 1;
        s_nW = (s_xmax - s_xmin + 1) / 6 + 1;
        s_T = s_nH * s_nW;
    }
    __syncthreads();
    const int nH = s_nH, nW = s_nW, T = s_T;
    const int ymin = s_ymin, xmin = s_xmin;

    // shift + center occupancy (r%6: 1 -> none; 0 -> tile q-1; 2..5 -> tile q)
#pragma unroll
    for (int j = 0; j < 4; j++) {
        const int y = py[j] - ymin, x = px[j] - xmin;
        py[j] = y; px[j] = x;
        const int qy = y / 6, ry = y - 6 * qy;
        const int qx = x / 6, rx = x - 6 * qx;
        const int cy = (ry == 1) ? -1 : ((ry == 0) ? qy - 1 : qy);
        const int cx = (rx == 1) ? -1 : ((rx == 0) ? qx - 1 : qx);
        if (cy >= 0 && cx >= 0) s_mask[cy * nW + cx] = 1;
    }
    __syncthreads();

    // inclusive scan of flags over T (<=441)
    {
        const int w = tid >> 5, lane = tid & 31;
        const int f = (tid < T) ? (int)s_mask[tid] : 0;
        int v = f;
        for (int off = 1; off < 32; off <<= 1) {
            const int t = __shfl_up_sync(0xffffffffu, v, off);
            if (lane >= off) v += t;
        }
        if (lane == 31) s_ws[w] = v;
        __syncthreads();
        if (w == 0 && lane < 16) {
            int sv = s_ws[lane];
            for (int off = 1; off < 16; off <<= 1) {
                const int t = __shfl_up_sync(0xffffu, sv, off);
                if (lane >= off) sv += t;
            }
            s_ws[lane] = sv;
        }
        __syncthreads();
        const int pre = (w > 0) ? s_ws[w - 1] : 0;
        s_slot[tid] = (short)(f ? (pre + v - 1) : -1);
        if (tid == 0) g_selcnt[b] = s_ws[15];
    }
    __syncthreads();

    // scatter points into per-slot lists (each point covers <=2x2 windows)
#pragma unroll
    for (int j = 0; j < 4; j++) {
        const int y = py[j], x = px[j];
        const int n = tid + j * 512;
        const int ilo = (y > 8) ? (y - 3) / 6 : 0;
        int       ihi = y / 6;  if (ihi > nH - 1) ihi = nH - 1;
        const int jlo = (x > 8) ? (x - 3) / 6 : 0;
        int       jhi = x / 6;  if (jhi > nW - 1) jhi = nW - 1;
        for (int i = ilo; i <= ihi; i++)
            for (int jj = jlo; jj <= jhi; jj++) {
                const int slot = s_slot[i * nW + jj];
                if (slot >= 0) {
                    const int pos = atomicAdd(&s_cnt[slot], 1);
                    g_list[(b * SLOTMAX + slot) * CELLS + pos] =
                        ((y - i * 6) * TSZ + (x - jj * 6)) << 16 | n;
                }
            }
    }
    __syncthreads();
    g_cnt[b * SLOTMAX + tid] = s_cnt[tid];
}

// ---------------------------------------------------------------------------
// tiles: zero+fill dense [64][81] chunk in smem; emit first part via one TMA
// bulk store (async) while all threads STG.128 the second part.
// tma_n = floats in TMA part (16B-multiple); head as before.
// ---------------------------------------------------------------------------
__global__ __launch_bounds__(256, 8) void tiles_kernel(const float* __restrict__ features,
                                                       float* __restrict__ out,
                                                       int ns_count, int head, int tma_n)
{
    const int s     = blockIdx.x >> 3;          // tile
    const int chunk = blockIdx.x & (NCHUNK - 1);
    const int tid = threadIdx.x;

    __shared__ alignas(16) float sval[CHUNK_ELEMS + 8];
    __shared__ short s_cell[CELLS], s_pn[CELLS];

    // per-thread metadata from broadcast loads
    const int c0 = g_selcnt[0], c1 = g_selcnt[1], c2 = g_selcnt[2];
    int b, local = s;
    if (s < c0)                { b = 0; }
    else if (s < c0 + c1)      { b = 1; local = s - c0; }
    else if (s < c0 + c1 + c2) { b = 2; local = s - c0 - c1; }
    else                       { b = 3; local = s - c0 - c1 - c2; }
    const int cnt = g_cnt[b * SLOTMAX + local];

    if (tid < CELLS) {
        const int e = g_list[(b * SLOTMAX + local) * CELLS + tid];
        if (tid < cnt) {
            s_cell[tid] = (short)(e >> 16);
            s_pn[tid]   = (short)(e & 0xffff);
        }
    }
    if (tid == 0 && ns_count > 0 && chunk == 0) out[s] = (float)b;   // f_ns

    // zero staging buffer
    {
        const float4 z = make_float4(0.f, 0.f, 0.f, 0.f);
        for (int i = tid; i < (CHUNK_ELEMS + 8) / 4; i += 256)
            ((float4*)sval)[i] = z;
    }
    __syncthreads();

    const float* __restrict__ fb = features + (size_t)b * (NP * NC) + chunk * CHUNK;
    const int ofs = (4 - head) & 3;             // (ofs+head) % 4 == 0

    // fill: coalesced LDG rows; STS stride-81 words (81 odd -> conflict-free)
    for (int i = tid; i < cnt * CHUNK; i += 256) {
        const int p = i >> 6, c = i & (CHUNK - 1);
        sval[ofs + c * CELLS + (int)s_cell[p]] = __ldg(fb + (int)s_pn[p] * NC + c);
    }
    __syncthreads();

    // emit
    float* __restrict__ oc = out + (size_t)ns_count + (size_t)s * TILE_ELEMS
                                 + (size_t)chunk * CHUNK_ELEMS;
    const int tail = (CHUNK_ELEMS - head) & 3;

    // 1) TMA bulk store of floats [head, head+tma_n)  (async on TMA engine)
    if (tid == 0) {
        asm volatile("fence.proxy.async.shared::cta;" ::: "memory");
        unsigned sptr = (unsigned)__cvta_generic_to_shared(sval + ofs + head);
        asm volatile("cp.async.bulk.global.shared::cta.bulk_group [%0], [%1], %2;"
                     :: "l"(oc + head), "r"(sptr), "r"((unsigned)tma_n * 4u) : "memory");
        asm volatile("cp.async.bulk.commit_group;" ::: "memory");
        // head/tail scalars while the bulk copy runs
        for (int j = 0; j < head; j++)
            __stcs(oc + j, sval[ofs + j]);
        for (int j = CHUNK_ELEMS - tail; j < CHUNK_ELEMS; j++)
            __stcs(oc + j, sval[ofs + j]);
    }

    // 2) STG.128 of floats [head+tma_n, CHUNK_ELEMS-tail) by all threads
    {
        const int j0 = head + tma_n;
        const int nb4 = (CHUNK_ELEMS - tail - j0) >> 2;
#pragma unroll 4
        for (int k = tid; k < nb4; k += 256) {
            const int j = j0 + (k << 2);
            const float4 v = *(const float4*)(sval + ofs + j);
            __stcs((float4*)(oc + j), v);
        }
    }

    // guard smem reuse: TMA must finish reading sval before block retires
    if (tid == 0)
        asm volatile("cp.async.bulk.wait_group.read 0;" ::: "memory");
}

// ---------------------------------------------------------------------------
extern "C" void kernel_launch(void* const* d_in, const int* in_sizes, int n_in,
                              void* d_out, int out_size)
{
    int fi = 0;
    for (int i = 0; i < n_in; i++)
        if (in_sizes[i] == NB * NP * NC) fi = i;
    const float* features = (const float*)d_in[fi];
    const void* ys = nullptr;
    const void* xs = nullptr;
    for (int i = 0; i < n_in; i++) {
        if (i == fi) continue;
        if (!ys) ys = d_in[i];
        else if (!xs) xs = d_in[i];
    }

    setup_kernel<<<NB, 512>>>(ys, xs);

    int K, ns_count;
    if (out_size % (TILE_ELEMS + 1) == 0) {
        K = out_size / (TILE_ELEMS + 1);
        ns_count = K;
    } else {
        K = out_size / TILE_ELEMS;
        ns_count = 0;
    }
    if (K <= 0) return;
    if (K > NB * SLOTMAX) K = NB * SLOTMAX;

    const int head = (4 - (ns_count & 3)) & 3;
    const int tail = (CHUNK_ELEMS - head) & 3;
    const int mid  = CHUNK_ELEMS - head - tail;     // multiple of 4
    const int tma_n = (mid / 2) & ~3;               // TMA half, 16B multiple

    tiles_kernel<<<K * NCHUNK, 256>>>(features, (float*)d_out, ns_count, head, tma_n);
}

// round 10
// speedup vs baseline: 1.2268x; 1.2268x over previous
#include <cuda_runtime.h>
#include <stdint.h>

// ---------------------------------------------------------------------------
// TiledFeaturesMap: B=4, N=2048, C=512, FS=1, T_SZ=9, T_STEP=6, T_CUT=2
// Output: float32 [ f_ns (K) | f_tiles (K*512*81) ], K = out_size/41473.
// tiles_kernel: per (tile, 64-ch chunk) block; no zero phase — an 81-bit
// occupancy bitmap routes empty float4s straight to constant-zero STG.128.
// ---------------------------------------------------------------------------

#define NB 4
#define NP 2048
#define NC 512
#define TSZ 9
#define CELLS 81
#define TILE_ELEMS 41472
#define SLOTMAX 512
#define CHUNK 64                        // channels per block
#define NCHUNK (NC / CHUNK)             // 8
#define CHUNK_ELEMS (CHUNK * CELLS)     // 5184

__device__ int g_selcnt[NB];
__device__ int g_cnt[NB * SLOTMAX];
__device__ int g_list[NB * SLOTMAX * CELLS];   // (cell<<16)|n

// ---------------------------------------------------------------------------
// setup: 4 blocks (one per batch) x 512 threads.
// ---------------------------------------------------------------------------
__global__ __launch_bounds__(512) void setup_kernel(const void* __restrict__ ys_raw,
                                                    const void* __restrict__ xs_raw)
{
    const int b = blockIdx.x;
    const int tid = threadIdx.x;

    __shared__ int s_bad, s_ymin, s_ymax, s_xmin, s_xmax;
    __shared__ unsigned char s_mask[512];
    __shared__ short s_slot[512];
    __shared__ int s_cnt[512];
    __shared__ int s_ws[16];
    __shared__ int s_nH, s_nW, s_T;

    if (tid == 0) { s_bad = 0; s_ymin = 1 << 30; s_ymax = -1; s_xmin = 1 << 30; s_xmax = -1; }
    s_mask[tid] = 0;
    s_cnt[tid] = 0;
    __syncthreads();

    // dtype detect (int64 LE: odd 32-bit words all 0)
    {
        const int* yw = (const int*)ys_raw;
        const int* xw = (const int*)xs_raw;
        int bad = 0;
        for (int i = b * 2 * NP + 1 + 2 * tid; i < (b + 1) * 2 * NP; i += 1024)
            bad |= yw[i] | xw[i];
        bad = __reduce_or_sync(0xffffffffu, bad);
        if ((tid & 31) == 0 && bad) atomicOr(&s_bad, 1);
    }
    __syncthreads();
    const bool is64 = (s_bad == 0);

    int py[4], px[4];
#pragma unroll
    for (int j = 0; j < 4; j++) {
        const int idx = b * NP + tid + j * 512;
        if (is64) {
            py[j] = (int)((const long long*)ys_raw)[idx];
            px[j] = (int)((const long long*)xs_raw)[idx];
        } else {
            py[j] = ((const int*)ys_raw)[idx];
            px[j] = ((const int*)xs_raw)[idx];
        }
    }
    {
        int ymn = py[0], ymx = py[0], xmn = px[0], xmx = px[0];
#pragma unroll
        for (int j = 1; j < 4; j++) {
            ymn = min(ymn, py[j]); ymx = max(ymx, py[j]);
            xmn = min(xmn, px[j]); xmx = max(xmx, px[j]);
        }
        ymn = __reduce_min_sync(0xffffffffu, ymn);
        ymx = __reduce_max_sync(0xffffffffu, ymx);
        xmn = __reduce_min_sync(0xffffffffu, xmn);
        xmx = __reduce_max_sync(0xffffffffu, xmx);
        if ((tid & 31) == 0) {
            atomicMin(&s_ymin, ymn); atomicMax(&s_ymax, ymx);
            atomicMin(&s_xmin, xmn); atomicMax(&s_xmax, xmx);
        }
    }
    __syncthreads();
    if (tid == 0) {
        s_nH = (s_ymax - s_ymin + 1) / 6 + 1;
        s_nW = (s_xmax - s_xmin + 1) / 6 + 1;
        s_T = s_nH * s_nW;
    }
    __syncthreads();
    const int nH = s_nH, nW = s_nW, T = s_T;
    const int ymin = s_ymin, xmin = s_xmin;

    // shift + center occupancy (r%6: 1 -> none; 0 -> tile q-1; 2..5 -> tile q)
#pragma unroll
    for (int j = 0; j < 4; j++) {
        const int y = py[j] - ymin, x = px[j] - xmin;
        py[j] = y; px[j] = x;
        const int qy = y / 6, ry = y - 6 * qy;
        const int qx = x / 6, rx = x - 6 * qx;
        const int cy = (ry == 1) ? -1 : ((ry == 0) ? qy - 1 : qy);
        const int cx = (rx == 1) ? -1 : ((rx == 0) ? qx - 1 : qx);
        if (cy >= 0 && cx >= 0) s_mask[cy * nW + cx] = 1;
    }
    __syncthreads();

    // inclusive scan of flags over T (<=441)
    {
        const int w = tid >> 5, lane = tid & 31;
        const int f = (tid < T) ? (int)s_mask[tid] : 0;
        int v = f;
        for (int off = 1; off < 32; off <<= 1) {
            const int t = __shfl_up_sync(0xffffffffu, v, off);
            if (lane >= off) v += t;
        }
        if (lane == 31) s_ws[w] = v;
        __syncthreads();
        if (w == 0 && lane < 16) {
            int sv = s_ws[lane];
            for (int off = 1; off < 16; off <<= 1) {
                const int t = __shfl_up_sync(0xffffu, sv, off);
                if (lane >= off) sv += t;
            }
            s_ws[lane] = sv;
        }
        __syncthreads();
        const int pre = (w > 0) ? s_ws[w - 1] : 0;
        s_slot[tid] = (short)(f ? (pre + v - 1) : -1);
        if (tid == 0) g_selcnt[b] = s_ws[15];
    }
    __syncthreads();

    // scatter points into per-slot lists (each point covers <=2x2 windows)
#pragma unroll
    for (int j = 0; j < 4; j++) {
        const int y = py[j], x = px[j];
        const int n = tid + j * 512;
        const int ilo = (y > 8) ? (y - 3) / 6 : 0;
        int       ihi = y / 6;  if (ihi > nH - 1) ihi = nH - 1;
        const int jlo = (x > 8) ? (x - 3) / 6 : 0;
        int       jhi = x / 6;  if (jhi > nW - 1) jhi = nW - 1;
        for (int i = ilo; i <= ihi; i++)
            for (int jj = jlo; jj <= jhi; jj++) {
                const int slot = s_slot[i * nW + jj];
                if (slot >= 0) {
                    const int pos = atomicAdd(&s_cnt[slot], 1);
                    g_list[(b * SLOTMAX + slot) * CELLS + pos] =
                        ((y - i * 6) * TSZ + (x - jj * 6)) << 16 | n;
                }
            }
    }
    __syncthreads();
    g_cnt[b * SLOTMAX + tid] = s_cnt[tid];
}

// ---------------------------------------------------------------------------
// tiles: fill only the occupied cells' columns in smem (coalesced LDG,
// conflict-free stride-81 STS); emit with an occupancy bitmap: empty float4
// -> constant zero STG.128 (no smem read), else predicated per-element LDS.
// Chunk-linear index == smem index, so addressing needs no cell tracking.
// ---------------------------------------------------------------------------
__global__ __launch_bounds__(256, 8) void tiles_kernel(const float* __restrict__ features,
                                                       float* __restrict__ out,
                                                       int ns_count, int head)
{
    const int s     = blockIdx.x >> 3;          // tile
    const int chunk = blockIdx.x & (NCHUNK - 1);
    const int tid = threadIdx.x;

    __shared__ alignas(16) float sval[CHUNK_ELEMS + 8];
    __shared__ short s_cell[CELLS], s_pn[CELLS];
    __shared__ unsigned s_bm[3];                // 81-bit occupancy bitmap

    // per-thread metadata from broadcast loads
    const int c0 = g_selcnt[0], c1 = g_selcnt[1], c2 = g_selcnt[2];
    int b, local = s;
    if (s < c0)                { b = 0; }
    else if (s < c0 + c1)      { b = 1; local = s - c0; }
    else if (s < c0 + c1 + c2) { b = 2; local = s - c0 - c1; }
    else                       { b = 3; local = s - c0 - c1 - c2; }
    const int cnt = g_cnt[b * SLOTMAX + local];

    if (tid < 3) s_bm[tid] = 0;
    __syncthreads();
    if (tid < cnt) {
        const int e = g_list[(b * SLOTMAX + local) * CELLS + tid];
        const int cell = e >> 16;
        s_cell[tid] = (short)cell;
        s_pn[tid]   = (short)(e & 0xffff);
        atomicOr(&s_bm[cell >> 5], 1u << (cell & 31));
    }
    if (tid == 0 && ns_count > 0 && chunk == 0) out[s] = (float)b;   // f_ns
    __syncthreads();

    // bitmap into registers; replicate wrap (bit 81+i == cell i)
    const unsigned bm0 = s_bm[0], bm1 = s_bm[1], bm2r = s_bm[2];
    const unsigned bm2 = bm2r | (bm0 << 17);            // bits 64..95
    const unsigned bm3 = (bm0 >> 15) | (bm1 << 17);     // bits 96..127

    const float* __restrict__ fb = features + (size_t)b * (NP * NC) + chunk * CHUNK;
    const int ofs = (4 - head) & 3;             // (ofs+head) % 4 == 0

    // fill occupied columns only: coalesced LDG rows; STS stride-81 words
    for (int i = tid; i < cnt * CHUNK; i += 256) {
        const int p = i >> 6, c = i & (CHUNK - 1);
        sval[ofs + c * CELLS + (int)s_cell[p]] = __ldg(fb + (int)s_pn[p] * NC + c);
    }
    __syncthreads();

    // emit
    float* __restrict__ oc = out + (size_t)ns_count + (size_t)s * TILE_ELEMS
                                 + (size_t)chunk * CHUNK_ELEMS;
    const int tail = (CHUNK_ELEMS - head) & 3;

    if (tid < head) {                           // head scalars: cell == lin
        const float v = ((bm0 >> tid) & 1u) ? sval[ofs + tid] : 0.0f;
        __stcs(oc + tid, v);
    }

    const int nb4 = (CHUNK_ELEMS - head - tail) >> 2;
    int lin = head + tid * 4;
    unsigned cc = (unsigned)lin % 81u;          // one mod per thread

#pragma unroll 2
    for (int k = tid; k < nb4; k += 256) {
        unsigned lo, hi;
        if (cc < 32)      { lo = bm0; hi = bm1; }
        else if (cc < 64) { lo = bm1; hi = bm2; }
        else              { lo = bm2; hi = bm3; }
        const unsigned sel = __funnelshift_r(lo, hi, cc) & 15u;

        float4 v = make_float4(0.f, 0.f, 0.f, 0.f);
        if (sel) {
            if (sel & 1u) v.x = sval[ofs + lin];
            if (sel & 2u) v.y = sval[ofs + lin + 1];
            if (sel & 4u) v.z = sval[ofs + lin + 2];
            if (sel & 8u) v.w = sval[ofs + lin + 3];
        }
        __stcs((float4*)(oc + lin), v);

        lin += 1024;                             // 256 threads * 4 elems
        cc += 52; if (cc >= 81u) cc -= 81u;      // 1024 mod 81 == 52
    }

    for (int k = tid; k < tail; k += 256) {
        const int l = head + (nb4 << 2) + k;
        const unsigned ce = (unsigned)l % 81u;
        unsigned w = (ce < 32) ? bm0 : (ce < 64) ? bm1 : bm2;
        const float v = ((w >> (ce & 31u)) & 1u) ? sval[ofs + l] : 0.0f;
        __stcs(oc + l, v);
    }
}

// ---------------------------------------------------------------------------
extern "C" void kernel_launch(void* const* d_in, const int* in_sizes, int n_in,
                              void* d_out, int out_size)
{
    int fi = 0;
    for (int i = 0; i < n_in; i++)
        if (in_sizes[i] == NB * NP * NC) fi = i;
    const float* features = (const float*)d_in[fi];
    const void* ys = nullptr;
    const void* xs = nullptr;
    for (int i = 0; i < n_in; i++) {
        if (i == fi) continue;
        if (!ys) ys = d_in[i];
        else if (!xs) xs = d_in[i];
    }

    setup_kernel<<<NB, 512>>>(ys, xs);

    int K, ns_count;
    if (out_size % (TILE_ELEMS + 1) == 0) {
        K = out_size / (TILE_ELEMS + 1);
        ns_count = K;
    } else {
        K = out_size / TILE_ELEMS;
        ns_count = 0;
    }
    if (K <= 0) return;
    if (K > NB * SLOTMAX) K = NB * SLOTMAX;

    const int head = (4 - (ns_count & 3)) & 3;
    tiles_kernel<<<K * NCHUNK, 256>>>(features, (float*)d_out, ns_count, head);
}